// round 15
// baseline (speedup 1.0000x reference)
#include <cuda_runtime.h>

#define N_NODES 50000
#define R_REL 51
#define F_DIM 32
#define E_DIM 32
#define C_DIM 16
#define B_BASES 30
#define NNZ_MAX 2001024
#define CHUNKS 64           // tasks per relation bucket (warp-level stealing)
#define N_TASKS (R_REL * CHUNKS)

typedef unsigned long long ull;
typedef unsigned int uint;

// ---- scratch (__device__ globals: no allocation allowed) -------------------
__device__ float g_w1[R_REL * F_DIM * E_DIM];            // [r][f][e]  208 KB
__device__ float g_w2[R_REL * E_DIM * C_DIM];            // [r][h][c]  104 KB
__device__ __align__(16) float g_h1[N_NODES * E_DIM];    // 6.4 MB
__device__ unsigned g_hist[R_REL];
__device__ unsigned g_cursor[R_REL];   // post-scatter: inclusive prefix end of bucket r
__device__ unsigned g_done;
__device__ unsigned g_ticket1, g_ticket2;
__device__ __align__(16) ull g_meta[NNZ_MAX];            // (v_bits<<32)|(n<<16)|m

// ---- packed f32x2 helpers --------------------------------------------------
__device__ __forceinline__ ull pack2(float lo, float hi) {
    ull r; asm("mov.b64 %0,{%1,%2};" : "=l"(r) : "f"(lo), "f"(hi)); return r;
}
__device__ __forceinline__ void unpack2(ull v, float& lo, float& hi) {
    asm("mov.b64 {%0,%1},%2;" : "=f"(lo), "=f"(hi) : "l"(v));
}
__device__ __forceinline__ ull ffma2(ull a, ull b, ull c) {
    ull d; asm("fma.rn.f32x2 %0,%1,%2,%3;" : "=l"(d) : "l"(a), "l"(b), "l"(c)); return d;
}
__device__ __forceinline__ ull fadd2(ull a, ull b) {
    ull d; asm("add.rn.f32x2 %0,%1,%2;" : "=l"(d) : "l"(a), "l"(b)); return d;
}
__device__ __forceinline__ ull fmul2(ull a, ull b) {
    ull d; asm("mul.rn.f32x2 %0,%1,%2;" : "=l"(d) : "l"(a), "l"(b)); return d;
}
__device__ __forceinline__ void red_add_v4(float* p, float a, float b, float c, float d) {
    asm volatile("red.global.add.v4.f32 [%0], {%1,%2,%3,%4};"
                 :: "l"(p), "f"(a), "f"(b), "f"(c), "f"(d) : "memory");
}
__device__ __forceinline__ ull shfl_xor_u64(ull v, int mask) {
    uint lo = (uint)v, hi = (uint)(v >> 32);
    lo = __shfl_xor_sync(0xffffffffu, lo, mask);
    hi = __shfl_xor_sync(0xffffffffu, hi, mask);
    return ((ull)hi << 32) | lo;
}
__device__ __forceinline__ ulonglong2 ldg_u64x2(const ulonglong2* p) {
    ulonglong2 q;
    asm("ld.global.nc.v2.u64 {%0,%1}, [%2];" : "=l"(q.x), "=l"(q.y) : "l"(p));
    return q;
}

// ---------------------------------------------------------------------------
// Fused: per-relation weights + zero hist/done/ticket1 + zero g_h1.
// ---------------------------------------------------------------------------
__global__ void compute_w_kernel(const float* __restrict__ comps1,
                                 const float* __restrict__ bases1,
                                 const float* __restrict__ comps2,
                                 const float* __restrict__ bases2) {
    int idx = blockIdx.x * blockDim.x + threadIdx.x;
    const int total1 = R_REL * F_DIM * E_DIM;
    const int total2 = R_REL * E_DIM * C_DIM;
    if (idx < total1) {
        int r = idx / (F_DIM * E_DIM);
        int fe = idx - r * (F_DIM * E_DIM);
        float acc = 0.f;
#pragma unroll
        for (int b = 0; b < B_BASES; b++)
            acc = fmaf(comps1[r * B_BASES + b], bases1[b * (F_DIM * E_DIM) + fe], acc);
        g_w1[idx] = acc;
    }
    if (idx < total2) {
        int r = idx / (E_DIM * C_DIM);
        int hc = idx - r * (E_DIM * C_DIM);
        float acc = 0.f;
#pragma unroll
        for (int b = 0; b < B_BASES; b++)
            acc = fmaf(comps2[r * B_BASES + b], bases2[b * (E_DIM * C_DIM) + hc], acc);
        g_w2[idx] = acc;
    }
    if (idx < R_REL) g_hist[idx] = 0;
    if (idx == 0) { g_done = 0; g_ticket1 = 0; }
    float4* h4 = (float4*)g_h1;
    const int nh4 = N_NODES * E_DIM / 4;
    for (int i = idx; i < nh4; i += gridDim.x * blockDim.x)
        h4[i] = make_float4(0.f, 0.f, 0.f, 0.f);
}

// ---------------------------------------------------------------------------
// Fused: histogram + (last block) exclusive-scan -> g_cursor + out = bias2.
// ---------------------------------------------------------------------------
__global__ void hist_kernel(const int* __restrict__ rows, int nnz,
                            float* __restrict__ out,
                            const float* __restrict__ bias2) {
    __shared__ unsigned sh[R_REL];
    if (threadIdx.x < R_REL) sh[threadIdx.x] = 0;
    __syncthreads();
    int gsz = gridDim.x * blockDim.x;
    for (int e = blockIdx.x * blockDim.x + threadIdx.x; e < nnz; e += gsz)
        atomicAdd(&sh[(unsigned)rows[e] / N_NODES], 1u);
    for (int i = blockIdx.x * blockDim.x + threadIdx.x; i < N_NODES * C_DIM; i += gsz)
        out[i] = bias2[i & (C_DIM - 1)];
    __syncthreads();
    if (threadIdx.x < R_REL) atomicAdd(&g_hist[threadIdx.x], sh[threadIdx.x]);
    __threadfence();
    __syncthreads();
    if (threadIdx.x == 0) {
        unsigned t = atomicAdd(&g_done, 1u);
        if (t == gridDim.x - 1) {
            unsigned s = 0;
            for (int r = 0; r < R_REL; r++) { g_cursor[r] = s; s += g_hist[r]; }
        }
    }
}

// Block-aggregated scatter into relation buckets.
#define SCATTER_CHUNK 8192
__global__ void scatter_kernel(const int* __restrict__ rows,
                               const int* __restrict__ cols,
                               const float* __restrict__ vals, int nnz) {
    __shared__ unsigned cnt[R_REL];
    __shared__ unsigned base[R_REL];
    int start = blockIdx.x * SCATTER_CHUNK;
    if (start >= nnz) return;
    int end = min(start + SCATTER_CHUNK, nnz);

    if (threadIdx.x < R_REL) cnt[threadIdx.x] = 0;
    __syncthreads();
    for (int e = start + threadIdx.x; e < end; e += blockDim.x)
        atomicAdd(&cnt[(unsigned)rows[e] / N_NODES], 1u);
    __syncthreads();
    if (threadIdx.x < R_REL) {
        base[threadIdx.x] = atomicAdd(&g_cursor[threadIdx.x], cnt[threadIdx.x]);
        cnt[threadIdx.x] = 0;
    }
    __syncthreads();
    for (int e = start + threadIdx.x; e < end; e += blockDim.x) {
        unsigned row = (unsigned)rows[e];
        unsigned r = row / N_NODES;
        unsigned n = row - r * N_NODES;
        unsigned pos = base[r] + atomicAdd(&cnt[r], 1u);
        g_meta[pos] = ((ull)__float_as_uint(vals[e]) << 32)
                    | (n << 16) | (unsigned)cols[e];
    }
}

__global__ void relu_bias_kernel(const float* __restrict__ bias1) {
    int idx = blockIdx.x * blockDim.x + threadIdx.x;
    if (idx == 0) g_ticket2 = 0;
    const int n4 = N_NODES * E_DIM / 4;
    if (idx < n4) {
        float4* h4 = (float4*)g_h1;
        const float4* b4 = (const float4*)bias1;
        float4 v = h4[idx];
        float4 b = b4[idx & (E_DIM / 4 - 1)];
        v.x = fmaxf(v.x + b.x, 0.f);
        v.y = fmaxf(v.y + b.y, 0.f);
        v.z = fmaxf(v.z + b.z, 0.f);
        v.w = fmaxf(v.w + b.w, 0.f);
        h4[idx] = v;
    }
}

// ---------------------------------------------------------------------------
// Layer 1: PERSISTENT, warp-level work stealing over (relation, chunk) tasks.
// Within a task the warp walks edges stride-1 (sequential meta lines).
// Partition per R14: fi = lane>>3 (4 x 8 f), eq = lane&7 (e = 4eq..4eq+3).
// Register weights (reloaded only when r changes); pack-free f32x2 mainloop;
// depth-2 meta / depth-1 x pipeline; shfl_xor(8,16) reduce; red.v4 x 8 lanes.
// ---------------------------------------------------------------------------
__global__ __launch_bounds__(256, 3)
void layer1_kernel(const float* __restrict__ x) {
    const int lane = threadIdx.x & 31;
    const int fi   = lane >> 3;                   // 0..3 (f-quarter: 8 f each)
    const int eq   = lane & 7;                    // e-quad: e = 4eq..4eq+3

    unsigned r_cur = 0xFFFFFFFFu;
    ull wA[4], wB[4], wC[4], wD[4];

    while (true) {
        unsigned t;
        if (lane == 0) t = atomicAdd(&g_ticket1, 1u);
        t = __shfl_sync(0xffffffffu, t, 0);
        if (t >= N_TASKS) return;
        unsigned r     = t / CHUNKS;
        unsigned chunk = t - r * CHUNKS;

        if (r != r_cur) {
            r_cur = r;
            const float* wr = g_w1 + r * (F_DIM * E_DIM) + (fi * 8) * E_DIM;
#pragma unroll
            for (int k = 0; k < 4; k++) {
                const float* w0 = wr + (2 * k) * E_DIM + eq * 4;
                const float* w1 = wr + (2 * k + 1) * E_DIM + eq * 4;
                wA[k] = pack2(w0[0], w1[0]);
                wB[k] = pack2(w0[1], w1[1]);
                wC[k] = pack2(w0[2], w1[2]);
                wD[k] = pack2(w0[3], w1[3]);
            }
        }

        const unsigned lo  = (r == 0) ? 0u : g_cursor[r - 1];
        const unsigned hi  = g_cursor[r];
        const unsigned len = hi - lo;
        unsigned e0 = lo + (unsigned)(((ull)len * chunk) / CHUNKS);
        const unsigned cend = lo + (unsigned)(((ull)len * (chunk + 1)) / CHUNKS);
        if (e0 >= cend) continue;
        const unsigned last = cend - 1;

        // pipeline prologue: meta depth 2, x depth 1 (stride-1 walk)
        unsigned e1 = e0 + 1;
        ull meta0 = g_meta[e0];
        ull meta1 = g_meta[e1 < cend ? e1 : last];
        const ulonglong2* xp =
            (const ulonglong2*)(x + (size_t)(meta0 & 0xFFFFu) * F_DIM + fi * 8);
        ulonglong2 c0 = ldg_u64x2(xp), c1 = ldg_u64x2(xp + 1);

        while (e0 < cend) {
            unsigned e2 = e1 + 1;
            ull meta2 = g_meta[e2 < cend ? e2 : last];
            const ulonglong2* xn =
                (const ulonglong2*)(x + (size_t)(meta1 & 0xFFFFu) * F_DIM + fi * 8);
            ulonglong2 n0 = ldg_u64x2(xn), n1 = ldg_u64x2(xn + 1);

            ull accA = 0, accB = 0, accC = 0, accD = 0;
            accA = ffma2(c0.x, wA[0], accA);  accB = ffma2(c0.x, wB[0], accB);
            accC = ffma2(c0.x, wC[0], accC);  accD = ffma2(c0.x, wD[0], accD);
            accA = ffma2(c0.y, wA[1], accA);  accB = ffma2(c0.y, wB[1], accB);
            accC = ffma2(c0.y, wC[1], accC);  accD = ffma2(c0.y, wD[1], accD);
            accA = ffma2(c1.x, wA[2], accA);  accB = ffma2(c1.x, wB[2], accB);
            accC = ffma2(c1.x, wC[2], accC);  accD = ffma2(c1.x, wD[2], accD);
            accA = ffma2(c1.y, wA[3], accA);  accB = ffma2(c1.y, wB[3], accB);
            accC = ffma2(c1.y, wC[3], accC);  accD = ffma2(c1.y, wD[3], accD);

            float sa0, sa1, sb0, sb1, sc0, sc1, sd0, sd1;
            unpack2(accA, sa0, sa1);  unpack2(accB, sb0, sb1);
            unpack2(accC, sc0, sc1);  unpack2(accD, sd0, sd1);
            ull p01 = pack2(sa0 + sa1, sb0 + sb1);    // (e0, e1)
            ull p23 = pack2(sc0 + sc1, sd0 + sd1);    // (e2, e3)
            p01 = fadd2(p01, shfl_xor_u64(p01, 8));
            p23 = fadd2(p23, shfl_xor_u64(p23, 8));
            p01 = fadd2(p01, shfl_xor_u64(p01, 16));
            p23 = fadd2(p23, shfl_xor_u64(p23, 16));
            if (fi == 0) {                             // 8 lanes per edge
                float v0 = __uint_as_float((uint)(meta0 >> 32));
                ull vp = pack2(v0, v0);
                float o0, o1, o2, o3;
                unpack2(fmul2(p01, vp), o0, o1);
                unpack2(fmul2(p23, vp), o2, o3);
                red_add_v4(g_h1 + (size_t)((meta0 >> 16) & 0xFFFFu) * E_DIM + eq * 4,
                           o0, o1, o2, o3);
            }
            e0 = e1; e1 = e2;
            meta0 = meta1; meta1 = meta2;
            c0 = n0; c1 = n1;
        }
    }
}

// ---------------------------------------------------------------------------
// Layer 2: PERSISTENT, warp-level stealing; 2 edges per warp per iteration.
// half = lane>>4 picks edge; fi = (hl>>2) (4 x 8 f), cq = hl&3 (c-quad).
// red.v4 from 4 lanes per edge; shfl_xor(4,8) reduce.
// ---------------------------------------------------------------------------
__global__ __launch_bounds__(256, 3)
void layer2_kernel(float* __restrict__ out) {
    const int lane = threadIdx.x & 31;
    const int half = lane >> 4;
    const int hl   = lane & 15;
    const int fi   = hl >> 2;                     // 0..3 (8 f each)
    const int cq   = hl & 3;                      // c-quad: c = 4cq..4cq+3

    unsigned r_cur = 0xFFFFFFFFu;
    ull wA[4], wB[4], wC[4], wD[4];

    while (true) {
        unsigned t;
        if (lane == 0) t = atomicAdd(&g_ticket2, 1u);
        t = __shfl_sync(0xffffffffu, t, 0);
        if (t >= N_TASKS) return;
        unsigned r     = t / CHUNKS;
        unsigned chunk = t - r * CHUNKS;

        if (r != r_cur) {
            r_cur = r;
            const float* wr = g_w2 + r * (E_DIM * C_DIM) + (fi * 8) * C_DIM;
#pragma unroll
            for (int k = 0; k < 4; k++) {
                const float* w0 = wr + (2 * k) * C_DIM + cq * 4;
                const float* w1 = wr + (2 * k + 1) * C_DIM + cq * 4;
                wA[k] = pack2(w0[0], w1[0]);
                wB[k] = pack2(w0[1], w1[1]);
                wC[k] = pack2(w0[2], w1[2]);
                wD[k] = pack2(w0[3], w1[3]);
            }
        }

        const unsigned lo  = (r == 0) ? 0u : g_cursor[r - 1];
        const unsigned hi  = g_cursor[r];
        const unsigned len = hi - lo;
        unsigned b0 = lo + (unsigned)(((ull)len * chunk) / CHUNKS);
        const unsigned cend = lo + (unsigned)(((ull)len * (chunk + 1)) / CHUNKS);
        if (b0 >= cend) continue;
        const unsigned last = cend - 1;

        // prologue (invalid edge -> clamp index, v forced to 0)
        unsigned eI0 = b0 + half;
        ull meta0 = g_meta[eI0 < cend ? eI0 : last];
        if (eI0 >= cend) meta0 &= 0xFFFFFFFFull;

        unsigned b1 = b0 + 2;
        unsigned eI1 = b1 + half;
        ull meta1 = g_meta[eI1 < cend ? eI1 : last];
        if (eI1 >= cend) meta1 &= 0xFFFFFFFFull;

        const ulonglong2* hp =
            (const ulonglong2*)(g_h1 + (size_t)(meta0 & 0xFFFFu) * E_DIM + fi * 8);
        ulonglong2 c0 = ldg_u64x2(hp), c1 = ldg_u64x2(hp + 1);

        while (b0 < cend) {
            unsigned b2 = b1 + 2;
            unsigned eI2 = b2 + half;
            ull meta2 = g_meta[eI2 < cend ? eI2 : last];
            if (eI2 >= cend) meta2 &= 0xFFFFFFFFull;

            const ulonglong2* hn =
                (const ulonglong2*)(g_h1 + (size_t)(meta1 & 0xFFFFu) * E_DIM + fi * 8);
            ulonglong2 n0 = ldg_u64x2(hn), n1 = ldg_u64x2(hn + 1);

            ull accA = 0, accB = 0, accC = 0, accD = 0;
            accA = ffma2(c0.x, wA[0], accA);  accB = ffma2(c0.x, wB[0], accB);
            accC = ffma2(c0.x, wC[0], accC);  accD = ffma2(c0.x, wD[0], accD);
            accA = ffma2(c0.y, wA[1], accA);  accB = ffma2(c0.y, wB[1], accB);
            accC = ffma2(c0.y, wC[1], accC);  accD = ffma2(c0.y, wD[1], accD);
            accA = ffma2(c1.x, wA[2], accA);  accB = ffma2(c1.x, wB[2], accB);
            accC = ffma2(c1.x, wC[2], accC);  accD = ffma2(c1.x, wD[2], accD);
            accA = ffma2(c1.y, wA[3], accA);  accB = ffma2(c1.y, wB[3], accB);
            accC = ffma2(c1.y, wC[3], accC);  accD = ffma2(c1.y, wD[3], accD);

            float sa0, sa1, sb0, sb1, sc0, sc1, sd0, sd1;
            unpack2(accA, sa0, sa1);  unpack2(accB, sb0, sb1);
            unpack2(accC, sc0, sc1);  unpack2(accD, sd0, sd1);
            ull p01 = pack2(sa0 + sa1, sb0 + sb1);    // (c0, c1)
            ull p23 = pack2(sc0 + sc1, sd0 + sd1);    // (c2, c3)
            p01 = fadd2(p01, shfl_xor_u64(p01, 4));
            p23 = fadd2(p23, shfl_xor_u64(p23, 4));
            p01 = fadd2(p01, shfl_xor_u64(p01, 8));
            p23 = fadd2(p23, shfl_xor_u64(p23, 8));
            if (fi == 0) {                             // 4 lanes per edge
                float v0 = __uint_as_float((uint)(meta0 >> 32));
                ull vp = pack2(v0, v0);
                float o0, o1, o2, o3;
                unpack2(fmul2(p01, vp), o0, o1);
                unpack2(fmul2(p23, vp), o2, o3);
                red_add_v4(out + (size_t)((meta0 >> 16) & 0xFFFFu) * C_DIM + cq * 4,
                           o0, o1, o2, o3);
            }
            b0 = b1; b1 = b2;
            meta0 = meta1; meta1 = meta2;
            c0 = n0; c1 = n1;
        }
    }
}

// ---------------------------------------------------------------------------
extern "C" void kernel_launch(void* const* d_in, const int* in_sizes, int n_in,
                              void* d_out, int out_size) {
    const float* features = (const float*)d_in[0];
    const float* vals     = (const float*)d_in[1];
    const float* comps1   = (const float*)d_in[2];
    const float* bases1   = (const float*)d_in[3];
    const float* bias1    = (const float*)d_in[4];
    const float* comps2   = (const float*)d_in[5];
    const float* bases2   = (const float*)d_in[6];
    const float* bias2    = (const float*)d_in[7];
    const int*   rows     = (const int*)d_in[8];
    const int*   cols     = (const int*)d_in[9];
    float*       out      = (float*)d_out;
    const int    nnz      = in_sizes[8];

    // 1. weights + zero hist/done/ticket1/h1
    compute_w_kernel<<<512, 256>>>(comps1, bases1, comps2, bases2);
    // 2. histogram + last-block scan + out=bias2
    hist_kernel<<<256, 256>>>(rows, nnz, out, bias2);
    // 3. bucket scatter (relation-sorted edge list; g_cursor -> bucket ends)
    scatter_kernel<<<(nnz + SCATTER_CHUNK - 1) / SCATTER_CHUNK, 512>>>(
        rows, cols, vals, nnz);
    // 4. layer 1 (persistent, warp work-stealing)
    layer1_kernel<<<148 * 3, 256>>>(features);
    // 5. bias + relu (+ zero ticket2)
    relu_bias_kernel<<<(N_NODES * E_DIM / 4 + 255) / 256, 256>>>(bias1);
    // 6. layer 2 (persistent, warp work-stealing)
    layer2_kernel<<<148 * 3, 256>>>(out);
}

// round 17
// speedup vs baseline: 1.0789x; 1.0789x over previous
#include <cuda_runtime.h>

#define N_NODES 50000
#define R_REL 51
#define F_DIM 32
#define E_DIM 32
#define C_DIM 16
#define B_BASES 30
#define NNZ_MAX 2001024
#define CHUNKS 256          // tasks per relation bucket (warp-level stealing)
#define N_TASKS (R_REL * CHUNKS)

typedef unsigned long long ull;
typedef unsigned int uint;

// ---- scratch (__device__ globals: no allocation allowed) -------------------
__device__ float g_w1[R_REL * F_DIM * E_DIM];            // [r][f][e]  208 KB
__device__ float g_w2[R_REL * E_DIM * C_DIM];            // [r][h][c]  104 KB
__device__ __align__(16) float g_h1[N_NODES * E_DIM];    // 6.4 MB
__device__ unsigned g_hist[R_REL];
__device__ unsigned g_cursor[R_REL];   // post-scatter: inclusive prefix end of bucket r
__device__ unsigned g_done;
__device__ unsigned g_ticket1, g_ticket2;
__device__ __align__(16) ull g_meta[NNZ_MAX];            // (v_bits<<32)|(n<<16)|m

// ---- packed f32x2 helpers --------------------------------------------------
__device__ __forceinline__ ull pack2(float lo, float hi) {
    ull r; asm("mov.b64 %0,{%1,%2};" : "=l"(r) : "f"(lo), "f"(hi)); return r;
}
__device__ __forceinline__ void unpack2(ull v, float& lo, float& hi) {
    asm("mov.b64 {%0,%1},%2;" : "=f"(lo), "=f"(hi) : "l"(v));
}
__device__ __forceinline__ ull ffma2(ull a, ull b, ull c) {
    ull d; asm("fma.rn.f32x2 %0,%1,%2,%3;" : "=l"(d) : "l"(a), "l"(b), "l"(c)); return d;
}
__device__ __forceinline__ ull fadd2(ull a, ull b) {
    ull d; asm("add.rn.f32x2 %0,%1,%2;" : "=l"(d) : "l"(a), "l"(b)); return d;
}
__device__ __forceinline__ ull fmul2(ull a, ull b) {
    ull d; asm("mul.rn.f32x2 %0,%1,%2;" : "=l"(d) : "l"(a), "l"(b)); return d;
}
__device__ __forceinline__ void red_add_v4(float* p, float a, float b, float c, float d) {
    asm volatile("red.global.add.v4.f32 [%0], {%1,%2,%3,%4};"
                 :: "l"(p), "f"(a), "f"(b), "f"(c), "f"(d) : "memory");
}
__device__ __forceinline__ ull shfl_xor_u64(ull v, int mask) {
    uint lo = (uint)v, hi = (uint)(v >> 32);
    lo = __shfl_xor_sync(0xffffffffu, lo, mask);
    hi = __shfl_xor_sync(0xffffffffu, hi, mask);
    return ((ull)hi << 32) | lo;
}
__device__ __forceinline__ ulonglong2 ldg_u64x2(const ulonglong2* p) {
    ulonglong2 q;
    asm("ld.global.nc.v2.u64 {%0,%1}, [%2];" : "=l"(q.x), "=l"(q.y) : "l"(p));
    return q;
}

// ---------------------------------------------------------------------------
// Fused: per-relation weights + zero hist/done/ticket1 + zero g_h1.
// ---------------------------------------------------------------------------
__global__ void compute_w_kernel(const float* __restrict__ comps1,
                                 const float* __restrict__ bases1,
                                 const float* __restrict__ comps2,
                                 const float* __restrict__ bases2) {
    int idx = blockIdx.x * blockDim.x + threadIdx.x;
    const int total1 = R_REL * F_DIM * E_DIM;
    const int total2 = R_REL * E_DIM * C_DIM;
    if (idx < total1) {
        int r = idx / (F_DIM * E_DIM);
        int fe = idx - r * (F_DIM * E_DIM);
        float acc = 0.f;
#pragma unroll
        for (int b = 0; b < B_BASES; b++)
            acc = fmaf(comps1[r * B_BASES + b], bases1[b * (F_DIM * E_DIM) + fe], acc);
        g_w1[idx] = acc;
    }
    if (idx < total2) {
        int r = idx / (E_DIM * C_DIM);
        int hc = idx - r * (E_DIM * C_DIM);
        float acc = 0.f;
#pragma unroll
        for (int b = 0; b < B_BASES; b++)
            acc = fmaf(comps2[r * B_BASES + b], bases2[b * (E_DIM * C_DIM) + hc], acc);
        g_w2[idx] = acc;
    }
    if (idx < R_REL) g_hist[idx] = 0;
    if (idx == 0) { g_done = 0; g_ticket1 = 0; }
    float4* h4 = (float4*)g_h1;
    const int nh4 = N_NODES * E_DIM / 4;
    for (int i = idx; i < nh4; i += gridDim.x * blockDim.x)
        h4[i] = make_float4(0.f, 0.f, 0.f, 0.f);
}

// ---------------------------------------------------------------------------
// Fused: histogram + (last block) exclusive-scan -> g_cursor + out = bias2.
// ---------------------------------------------------------------------------
__global__ void hist_kernel(const int* __restrict__ rows, int nnz,
                            float* __restrict__ out,
                            const float* __restrict__ bias2) {
    __shared__ unsigned sh[R_REL];
    if (threadIdx.x < R_REL) sh[threadIdx.x] = 0;
    __syncthreads();
    int gsz = gridDim.x * blockDim.x;
    for (int e = blockIdx.x * blockDim.x + threadIdx.x; e < nnz; e += gsz)
        atomicAdd(&sh[(unsigned)rows[e] / N_NODES], 1u);
    for (int i = blockIdx.x * blockDim.x + threadIdx.x; i < N_NODES * C_DIM; i += gsz)
        out[i] = bias2[i & (C_DIM - 1)];
    __syncthreads();
    if (threadIdx.x < R_REL) atomicAdd(&g_hist[threadIdx.x], sh[threadIdx.x]);
    __threadfence();
    __syncthreads();
    if (threadIdx.x == 0) {
        unsigned t = atomicAdd(&g_done, 1u);
        if (t == gridDim.x - 1) {
            unsigned s = 0;
            for (int r = 0; r < R_REL; r++) { g_cursor[r] = s; s += g_hist[r]; }
        }
    }
}

// Block-aggregated scatter into relation buckets.
#define SCATTER_CHUNK 8192
__global__ void scatter_kernel(const int* __restrict__ rows,
                               const int* __restrict__ cols,
                               const float* __restrict__ vals, int nnz) {
    __shared__ unsigned cnt[R_REL];
    __shared__ unsigned base[R_REL];
    int start = blockIdx.x * SCATTER_CHUNK;
    if (start >= nnz) return;
    int end = min(start + SCATTER_CHUNK, nnz);

    if (threadIdx.x < R_REL) cnt[threadIdx.x] = 0;
    __syncthreads();
    for (int e = start + threadIdx.x; e < end; e += blockDim.x)
        atomicAdd(&cnt[(unsigned)rows[e] / N_NODES], 1u);
    __syncthreads();
    if (threadIdx.x < R_REL) {
        base[threadIdx.x] = atomicAdd(&g_cursor[threadIdx.x], cnt[threadIdx.x]);
        cnt[threadIdx.x] = 0;
    }
    __syncthreads();
    for (int e = start + threadIdx.x; e < end; e += blockDim.x) {
        unsigned row = (unsigned)rows[e];
        unsigned r = row / N_NODES;
        unsigned n = row - r * N_NODES;
        unsigned pos = base[r] + atomicAdd(&cnt[r], 1u);
        g_meta[pos] = ((ull)__float_as_uint(vals[e]) << 32)
                    | (n << 16) | (unsigned)cols[e];
    }
}

__global__ void relu_bias_kernel(const float* __restrict__ bias1) {
    int idx = blockIdx.x * blockDim.x + threadIdx.x;
    if (idx == 0) g_ticket2 = 0;
    const int n4 = N_NODES * E_DIM / 4;
    if (idx < n4) {
        float4* h4 = (float4*)g_h1;
        const float4* b4 = (const float4*)bias1;
        float4 v = h4[idx];
        float4 b = b4[idx & (E_DIM / 4 - 1)];
        v.x = fmaxf(v.x + b.x, 0.f);
        v.y = fmaxf(v.y + b.y, 0.f);
        v.z = fmaxf(v.z + b.z, 0.f);
        v.w = fmaxf(v.w + b.w, 0.f);
        h4[idx] = v;
    }
}

// ---------------------------------------------------------------------------
// Layer 1: PERSISTENT, warp work-stealing; TWO edges per warp-iteration.
// Partition: fi = lane>>3 (4 x 8 f), eq = lane&7 (e = 4eq..4eq+3).
// Register weights (reloaded only when r changes); pack-free f32x2 mainloop;
// next-pair meta/x prefetched over the current pair's FFMA chain;
// shfl_xor(8,16) reduce; red.v4 from 8 lanes per edge.
// ---------------------------------------------------------------------------
__global__ __launch_bounds__(256, 2)
void layer1_kernel(const float* __restrict__ x) {
    const int lane = threadIdx.x & 31;
    const int fi   = lane >> 3;                   // 0..3 (f-quarter: 8 f each)
    const int eq   = lane & 7;                    // e-quad: e = 4eq..4eq+3

    unsigned r_cur = 0xFFFFFFFFu;
    ull wA[4], wB[4], wC[4], wD[4];

    while (true) {
        unsigned t;
        if (lane == 0) t = atomicAdd(&g_ticket1, 1u);
        t = __shfl_sync(0xffffffffu, t, 0);
        if (t >= N_TASKS) return;
        unsigned r     = t / CHUNKS;
        unsigned chunk = t - r * CHUNKS;

        if (r != r_cur) {
            r_cur = r;
            const float* wr = g_w1 + r * (F_DIM * E_DIM) + (fi * 8) * E_DIM;
#pragma unroll
            for (int k = 0; k < 4; k++) {
                const float* w0 = wr + (2 * k) * E_DIM + eq * 4;
                const float* w1 = wr + (2 * k + 1) * E_DIM + eq * 4;
                wA[k] = pack2(w0[0], w1[0]);
                wB[k] = pack2(w0[1], w1[1]);
                wC[k] = pack2(w0[2], w1[2]);
                wD[k] = pack2(w0[3], w1[3]);
            }
        }

        const unsigned lo  = (r == 0) ? 0u : g_cursor[r - 1];
        const unsigned hi  = g_cursor[r];
        const unsigned len = hi - lo;
        unsigned p0 = lo + (unsigned)(((ull)len * chunk) / CHUNKS);
        const unsigned cend = lo + (unsigned)(((ull)len * (chunk + 1)) / CHUNKS);
        if (p0 >= cend) continue;
        const unsigned last = cend - 1;

        // prologue: metas for pair0 and pair1; x for pair0 (edges A=p, B=p+1)
        ull mA0 = g_meta[p0];
        unsigned iB0 = p0 + 1;
        ull mB0 = g_meta[iB0 <= last ? iB0 : last];
        if (iB0 > last) mB0 &= 0xFFFFFFFFull;       // v = 0

        unsigned p1 = p0 + 2;
        ull mA1 = g_meta[p1 <= last ? p1 : last];
        if (p1 > last) mA1 &= 0xFFFFFFFFull;
        unsigned iB1 = p1 + 1;
        ull mB1 = g_meta[iB1 <= last ? iB1 : last];
        if (iB1 > last) mB1 &= 0xFFFFFFFFull;

        const ulonglong2* xa =
            (const ulonglong2*)(x + (size_t)(mA0 & 0xFFFFu) * F_DIM + fi * 8);
        const ulonglong2* xb =
            (const ulonglong2*)(x + (size_t)(mB0 & 0xFFFFu) * F_DIM + fi * 8);
        ulonglong2 a0 = ldg_u64x2(xa), a1 = ldg_u64x2(xa + 1);
        ulonglong2 b0 = ldg_u64x2(xb), b1 = ldg_u64x2(xb + 1);

        while (p0 < cend) {
            // meta prefetch for pair2
            unsigned p2 = p1 + 2;
            ull mA2 = g_meta[p2 <= last ? p2 : last];
            if (p2 > last) mA2 &= 0xFFFFFFFFull;
            unsigned iB2 = p2 + 1;
            ull mB2 = g_meta[iB2 <= last ? iB2 : last];
            if (iB2 > last) mB2 &= 0xFFFFFFFFull;
            // x prefetch for pair1
            const ulonglong2* xan =
                (const ulonglong2*)(x + (size_t)(mA1 & 0xFFFFu) * F_DIM + fi * 8);
            const ulonglong2* xbn =
                (const ulonglong2*)(x + (size_t)(mB1 & 0xFFFFu) * F_DIM + fi * 8);
            ulonglong2 na0 = ldg_u64x2(xan), na1 = ldg_u64x2(xan + 1);
            ulonglong2 nb0 = ldg_u64x2(xbn), nb1 = ldg_u64x2(xbn + 1);

            // ---- edge A ----
            {
                ull accA = 0, accB = 0, accC = 0, accD = 0;
                accA = ffma2(a0.x, wA[0], accA);  accB = ffma2(a0.x, wB[0], accB);
                accC = ffma2(a0.x, wC[0], accC);  accD = ffma2(a0.x, wD[0], accD);
                accA = ffma2(a0.y, wA[1], accA);  accB = ffma2(a0.y, wB[1], accB);
                accC = ffma2(a0.y, wC[1], accC);  accD = ffma2(a0.y, wD[1], accD);
                accA = ffma2(a1.x, wA[2], accA);  accB = ffma2(a1.x, wB[2], accB);
                accC = ffma2(a1.x, wC[2], accC);  accD = ffma2(a1.x, wD[2], accD);
                accA = ffma2(a1.y, wA[3], accA);  accB = ffma2(a1.y, wB[3], accB);
                accC = ffma2(a1.y, wC[3], accC);  accD = ffma2(a1.y, wD[3], accD);

                float sa0, sa1, sb0, sb1, sc0, sc1, sd0, sd1;
                unpack2(accA, sa0, sa1);  unpack2(accB, sb0, sb1);
                unpack2(accC, sc0, sc1);  unpack2(accD, sd0, sd1);
                ull p01 = pack2(sa0 + sa1, sb0 + sb1);
                ull p23 = pack2(sc0 + sc1, sd0 + sd1);
                p01 = fadd2(p01, shfl_xor_u64(p01, 8));
                p23 = fadd2(p23, shfl_xor_u64(p23, 8));
                p01 = fadd2(p01, shfl_xor_u64(p01, 16));
                p23 = fadd2(p23, shfl_xor_u64(p23, 16));
                if (fi == 0) {
                    float v0 = __uint_as_float((uint)(mA0 >> 32));
                    ull vp = pack2(v0, v0);
                    float o0, o1, o2, o3;
                    unpack2(fmul2(p01, vp), o0, o1);
                    unpack2(fmul2(p23, vp), o2, o3);
                    red_add_v4(g_h1 + (size_t)((mA0 >> 16) & 0xFFFFu) * E_DIM + eq * 4,
                               o0, o1, o2, o3);
                }
            }
            // ---- edge B (v == 0 on tail) ----
            {
                ull accA = 0, accB = 0, accC = 0, accD = 0;
                accA = ffma2(b0.x, wA[0], accA);  accB = ffma2(b0.x, wB[0], accB);
                accC = ffma2(b0.x, wC[0], accC);  accD = ffma2(b0.x, wD[0], accD);
                accA = ffma2(b0.y, wA[1], accA);  accB = ffma2(b0.y, wB[1], accB);
                accC = ffma2(b0.y, wC[1], accC);  accD = ffma2(b0.y, wD[1], accD);
                accA = ffma2(b1.x, wA[2], accA);  accB = ffma2(b1.x, wB[2], accB);
                accC = ffma2(b1.x, wC[2], accC);  accD = ffma2(b1.x, wD[2], accD);
                accA = ffma2(b1.y, wA[3], accA);  accB = ffma2(b1.y, wB[3], accB);
                accC = ffma2(b1.y, wC[3], accC);  accD = ffma2(b1.y, wD[3], accD);

                float sa0, sa1, sb0, sb1, sc0, sc1, sd0, sd1;
                unpack2(accA, sa0, sa1);  unpack2(accB, sb0, sb1);
                unpack2(accC, sc0, sc1);  unpack2(accD, sd0, sd1);
                ull p01 = pack2(sa0 + sa1, sb0 + sb1);
                ull p23 = pack2(sc0 + sc1, sd0 + sd1);
                p01 = fadd2(p01, shfl_xor_u64(p01, 8));
                p23 = fadd2(p23, shfl_xor_u64(p23, 8));
                p01 = fadd2(p01, shfl_xor_u64(p01, 16));
                p23 = fadd2(p23, shfl_xor_u64(p23, 16));
                if (fi == 0) {
                    float v0 = __uint_as_float((uint)(mB0 >> 32));
                    ull vp = pack2(v0, v0);
                    float o0, o1, o2, o3;
                    unpack2(fmul2(p01, vp), o0, o1);
                    unpack2(fmul2(p23, vp), o2, o3);
                    red_add_v4(g_h1 + (size_t)((mB0 >> 16) & 0xFFFFu) * E_DIM + eq * 4,
                               o0, o1, o2, o3);
                }
            }
            // shift pipeline
            p0 = p1; p1 = p2;
            mA0 = mA1; mB0 = mB1; mA1 = mA2; mB1 = mB2;
            a0 = na0; a1 = na1; b0 = nb0; b1 = nb1;
        }
    }
}

// ---------------------------------------------------------------------------
// Layer 2: PERSISTENT, warp-level stealing; 2 edges per warp per iteration.
// half = lane>>4 picks edge; fi = (hl>>2) (4 x 8 f), cq = hl&3 (c-quad).
// red.v4 from 4 lanes per edge; shfl_xor(4,8) reduce.
// ---------------------------------------------------------------------------
__global__ __launch_bounds__(256, 3)
void layer2_kernel(float* __restrict__ out) {
    const int lane = threadIdx.x & 31;
    const int half = lane >> 4;
    const int hl   = lane & 15;
    const int fi   = hl >> 2;                     // 0..3 (8 f each)
    const int cq   = hl & 3;                      // c-quad: c = 4cq..4cq+3

    unsigned r_cur = 0xFFFFFFFFu;
    ull wA[4], wB[4], wC[4], wD[4];

    while (true) {
        unsigned t;
        if (lane == 0) t = atomicAdd(&g_ticket2, 1u);
        t = __shfl_sync(0xffffffffu, t, 0);
        if (t >= N_TASKS) return;
        unsigned r     = t / CHUNKS;
        unsigned chunk = t - r * CHUNKS;

        if (r != r_cur) {
            r_cur = r;
            const float* wr = g_w2 + r * (E_DIM * C_DIM) + (fi * 8) * C_DIM;
#pragma unroll
            for (int k = 0; k < 4; k++) {
                const float* w0 = wr + (2 * k) * C_DIM + cq * 4;
                const float* w1 = wr + (2 * k + 1) * C_DIM + cq * 4;
                wA[k] = pack2(w0[0], w1[0]);
                wB[k] = pack2(w0[1], w1[1]);
                wC[k] = pack2(w0[2], w1[2]);
                wD[k] = pack2(w0[3], w1[3]);
            }
        }

        const unsigned lo  = (r == 0) ? 0u : g_cursor[r - 1];
        const unsigned hi  = g_cursor[r];
        const unsigned len = hi - lo;
        unsigned b0 = lo + (unsigned)(((ull)len * chunk) / CHUNKS);
        const unsigned cend = lo + (unsigned)(((ull)len * (chunk + 1)) / CHUNKS);
        if (b0 >= cend) continue;
        const unsigned last = cend - 1;

        unsigned eI0 = b0 + half;
        ull meta0 = g_meta[eI0 <= last ? eI0 : last];
        if (eI0 > last) meta0 &= 0xFFFFFFFFull;

        unsigned b1 = b0 + 2;
        unsigned eI1 = b1 + half;
        ull meta1 = g_meta[eI1 <= last ? eI1 : last];
        if (eI1 > last) meta1 &= 0xFFFFFFFFull;

        const ulonglong2* hp =
            (const ulonglong2*)(g_h1 + (size_t)(meta0 & 0xFFFFu) * E_DIM + fi * 8);
        ulonglong2 c0 = ldg_u64x2(hp), c1 = ldg_u64x2(hp + 1);

        while (b0 < cend) {
            unsigned b2 = b1 + 2;
            unsigned eI2 = b2 + half;
            ull meta2 = g_meta[eI2 <= last ? eI2 : last];
            if (eI2 > last) meta2 &= 0xFFFFFFFFull;

            const ulonglong2* hn =
                (const ulonglong2*)(g_h1 + (size_t)(meta1 & 0xFFFFu) * E_DIM + fi * 8);
            ulonglong2 n0 = ldg_u64x2(hn), n1 = ldg_u64x2(hn + 1);

            ull accA = 0, accB = 0, accC = 0, accD = 0;
            accA = ffma2(c0.x, wA[0], accA);  accB = ffma2(c0.x, wB[0], accB);
            accC = ffma2(c0.x, wC[0], accC);  accD = ffma2(c0.x, wD[0], accD);
            accA = ffma2(c0.y, wA[1], accA);  accB = ffma2(c0.y, wB[1], accB);
            accC = ffma2(c0.y, wC[1], accC);  accD = ffma2(c0.y, wD[1], accD);
            accA = ffma2(c1.x, wA[2], accA);  accB = ffma2(c1.x, wB[2], accB);
            accC = ffma2(c1.x, wC[2], accC);  accD = ffma2(c1.x, wD[2], accD);
            accA = ffma2(c1.y, wA[3], accA);  accB = ffma2(c1.y, wB[3], accB);
            accC = ffma2(c1.y, wC[3], accC);  accD = ffma2(c1.y, wD[3], accD);

            float sa0, sa1, sb0, sb1, sc0, sc1, sd0, sd1;
            unpack2(accA, sa0, sa1);  unpack2(accB, sb0, sb1);
            unpack2(accC, sc0, sc1);  unpack2(accD, sd0, sd1);
            ull p01 = pack2(sa0 + sa1, sb0 + sb1);
            ull p23 = pack2(sc0 + sc1, sd0 + sd1);
            p01 = fadd2(p01, shfl_xor_u64(p01, 4));
            p23 = fadd2(p23, shfl_xor_u64(p23, 4));
            p01 = fadd2(p01, shfl_xor_u64(p01, 8));
            p23 = fadd2(p23, shfl_xor_u64(p23, 8));
            if (fi == 0) {
                float v0 = __uint_as_float((uint)(meta0 >> 32));
                ull vp = pack2(v0, v0);
                float o0, o1, o2, o3;
                unpack2(fmul2(p01, vp), o0, o1);
                unpack2(fmul2(p23, vp), o2, o3);
                red_add_v4(out + (size_t)((meta0 >> 16) & 0xFFFFu) * C_DIM + cq * 4,
                           o0, o1, o2, o3);
            }
            b0 = b1; b1 = b2;
            meta0 = meta1; meta1 = meta2;
            c0 = n0; c1 = n1;
        }
    }
}

// ---------------------------------------------------------------------------
extern "C" void kernel_launch(void* const* d_in, const int* in_sizes, int n_in,
                              void* d_out, int out_size) {
    const float* features = (const float*)d_in[0];
    const float* vals     = (const float*)d_in[1];
    const float* comps1   = (const float*)d_in[2];
    const float* bases1   = (const float*)d_in[3];
    const float* bias1    = (const float*)d_in[4];
    const float* comps2   = (const float*)d_in[5];
    const float* bases2   = (const float*)d_in[6];
    const float* bias2    = (const float*)d_in[7];
    const int*   rows     = (const int*)d_in[8];
    const int*   cols     = (const int*)d_in[9];
    float*       out      = (float*)d_out;
    const int    nnz      = in_sizes[8];

    // 1. weights + zero hist/done/ticket1/h1
    compute_w_kernel<<<512, 256>>>(comps1, bases1, comps2, bases2);
    // 2. histogram + last-block scan + out=bias2
    hist_kernel<<<256, 256>>>(rows, nnz, out, bias2);
    // 3. bucket scatter (relation-sorted edge list; g_cursor -> bucket ends)
    scatter_kernel<<<(nnz + SCATTER_CHUNK - 1) / SCATTER_CHUNK, 512>>>(
        rows, cols, vals, nnz);
    // 4. layer 1 (persistent, 2 edges/warp-iter, fine-grained stealing)
    layer1_kernel<<<148 * 2, 256>>>(features);
    // 5. bias + relu (+ zero ticket2)
    relu_bias_kernel<<<(N_NODES * E_DIM / 4 + 255) / 256, 256>>>(bias1);
    // 6. layer 2 (persistent, fine-grained stealing)
    layer2_kernel<<<148 * 3, 256>>>(out);
}